// round 1
// baseline (speedup 1.0000x reference)
#include <cuda_runtime.h>
#include <math.h>

// ---------------- problem dims ----------------
#define UU      356
#define GATES   1424            // 4*U
#define BSZ     8192
#define TS      7
#define FENC    69
#define FDEC    45
#define DECFLAT (TS*UU)         // 2492
#define H1      1024
#define OUTN    168

// ---------------- scratch (device globals; no allocations allowed) ----------
__device__ float g_xw [(size_t)BSZ*TS*GATES];   // input projections, reused enc->dec
__device__ float g_z  [(size_t)BSZ*GATES];      // per-step pre-activation
__device__ float g_h  [(size_t)BSZ*UU];
__device__ float g_c  [(size_t)BSZ*UU];
__device__ float g_dec[(size_t)BSZ*DECFLAT];    // decoder hidden sequence, flattened
__device__ float g_t1 [(size_t)BSZ*H1];
__device__ float g_t2 [(size_t)BSZ*H1];

// ---------------- generic tiled SGEMM ----------------
// C[M,N] = act( A[M,K] @ B[K,N] (+ Cinit) (+ bias) ), all row-major.
#define BM 128
#define BN 128
#define BK 16
#define TM 8
#define TN 8

template<int ACT, bool BIAS, bool CINIT>
__global__ __launch_bounds__(256, 2)
void sgemm_kernel(int M, int N, int K,
                  const float* __restrict__ A, int lda,
                  const float* __restrict__ B, int ldb,
                  const float* __restrict__ bias,
                  const float* __restrict__ Ci, int ldci,
                  float* __restrict__ C, int ldc)
{
    __shared__ float As[BK][BM + 4];   // +4 pad: avoids worst-case store conflicts,
                                       // keeps rows 16B-aligned for LDS.128
    __shared__ float Bs[BK][BN];

    const int tid = threadIdx.x;
    const int tx  = tid & 15;          // N direction (16 threads)
    const int ty  = tid >> 4;          // M direction (16 threads)
    const int bm  = blockIdx.y * BM;
    const int bn  = blockIdx.x * BN;

    float acc[TM][TN];
    #pragma unroll
    for (int i = 0; i < TM; i++)
        #pragma unroll
        for (int j = 0; j < TN; j++) acc[i][j] = 0.f;

    for (int k0 = 0; k0 < K; k0 += BK) {
        // stage A tile (transposed into smem): 2048 elems / 256 thr = 8 each
        #pragma unroll
        for (int i = 0; i < 8; i++) {
            int e = tid + i * 256;
            int r = e >> 4;            // 0..127 (M within tile)
            int cc = e & 15;           // 0..15  (K within tile)
            int gr = bm + r, gc = k0 + cc;
            As[cc][r] = (gr < M && gc < K) ? A[(size_t)gr * lda + gc] : 0.f;
        }
        // stage B tile: coalesced along N
        #pragma unroll
        for (int i = 0; i < 8; i++) {
            int e = tid + i * 256;
            int r = e >> 7;            // 0..15 (K)
            int cc = e & 127;          // 0..127 (N)
            int gr = k0 + r, gc = bn + cc;
            Bs[r][cc] = (gr < K && gc < N) ? B[(size_t)gr * ldb + gc] : 0.f;
        }
        __syncthreads();

        #pragma unroll
        for (int k = 0; k < BK; k++) {
            float a_frag[TM], b_frag[TN];
            #pragma unroll
            for (int i = 0; i < TM; i++) a_frag[i] = As[k][ty * TM + i];
            #pragma unroll
            for (int j = 0; j < TN; j++) b_frag[j] = Bs[k][tx * TN + j];
            #pragma unroll
            for (int i = 0; i < TM; i++)
                #pragma unroll
                for (int j = 0; j < TN; j++)
                    acc[i][j] = fmaf(a_frag[i], b_frag[j], acc[i][j]);
        }
        __syncthreads();
    }

    // epilogue
    #pragma unroll
    for (int i = 0; i < TM; i++) {
        int gr = bm + ty * TM + i;
        if (gr >= M) continue;
        #pragma unroll
        for (int j = 0; j < TN; j++) {
            int gc = bn + tx * TN + j;
            if (gc >= N) continue;
            float v = acc[i][j];
            if (CINIT) v += Ci[(size_t)gr * ldci + gc];
            if (BIAS)  v += bias[gc];
            if (ACT == 1) v = fmaxf(v, 0.f);
            else if (ACT == 2) v = tanhf(v);
            C[(size_t)gr * ldc + gc] = v;
        }
    }
}

template<int ACT, bool BIAS, bool CINIT>
static inline void launch_gemm(int M, int N, int K,
                               const float* A, int lda,
                               const float* B, int ldb,
                               const float* bias,
                               const float* Ci, int ldci,
                               float* C, int ldc)
{
    dim3 grid((N + BN - 1) / BN, (M + BM - 1) / BM);
    sgemm_kernel<ACT, BIAS, CINIT><<<grid, 256>>>(M, N, K, A, lda, B, ldb,
                                                  bias, Ci, ldci, C, ldc);
}

// ---------------- LSTM gate pointwise ----------------
// z row layout: [i(356) | f(356) | g(356) | o(356)]
__global__ void lstm_gates_kernel(const float* __restrict__ z,
                                  float* __restrict__ h,
                                  float* __restrict__ c,
                                  float* __restrict__ dec_out, int t)
{
    int idx = blockIdx.x * blockDim.x + threadIdx.x;
    const int TOT = BSZ * UU;
    if (idx >= TOT) return;
    int b = idx / UU;
    int j = idx - b * UU;
    const float* zr = z + (size_t)b * GATES;
    float zi = zr[j];
    float zf = zr[UU + j];
    float zg = zr[2 * UU + j];
    float zo = zr[3 * UU + j];
    float ig = 1.f / (1.f + expf(-zi));
    float fg = 1.f / (1.f + expf(-zf));
    float gg = tanhf(zg);
    float og = 1.f / (1.f + expf(-zo));
    float cn = fg * c[idx] + ig * gg;
    c[idx] = cn;
    float hn = og * tanhf(cn);
    h[idx] = hn;
    if (dec_out)
        dec_out[(size_t)b * DECFLAT + t * UU + j] = hn;
}

// ---------------- driver ----------------
extern "C" void kernel_launch(void* const* d_in, const int* /*in_sizes*/, int /*n_in*/,
                              void* d_out, int /*out_size*/)
{
    const float* x     = (const float*)d_in[0];   // [8192,7,69]
    const float* m     = (const float*)d_in[1];   // [8192,7,45]
    const float* enc_W = (const float*)d_in[2];   // [69,1424]
    const float* enc_U = (const float*)d_in[3];   // [356,1424]
    const float* enc_b = (const float*)d_in[4];   // [1424]
    const float* dec_W = (const float*)d_in[5];   // [45,1424]
    const float* dec_U = (const float*)d_in[6];   // [356,1424]
    const float* dec_b = (const float*)d_in[7];   // [1424]
    const float* W_map = (const float*)d_in[8];   // [2492,1024]
    const float* b_map = (const float*)d_in[9];
    const float* W1    = (const float*)d_in[10];
    const float* b1    = (const float*)d_in[11];
    const float* W2    = (const float*)d_in[12];
    const float* b2    = (const float*)d_in[13];
    const float* W3    = (const float*)d_in[14];
    const float* b3    = (const float*)d_in[15];
    const float* W_out = (const float*)d_in[16];  // [1024,168]
    const float* b_out = (const float*)d_in[17];
    float* out = (float*)d_out;                   // [8192,168]

    float *xw, *z, *h, *c, *dec, *t1, *t2;
    cudaGetSymbolAddress((void**)&xw,  g_xw);
    cudaGetSymbolAddress((void**)&z,   g_z);
    cudaGetSymbolAddress((void**)&h,   g_h);
    cudaGetSymbolAddress((void**)&c,   g_c);
    cudaGetSymbolAddress((void**)&dec, g_dec);
    cudaGetSymbolAddress((void**)&t1,  g_t1);
    cudaGetSymbolAddress((void**)&t2,  g_t2);

    cudaMemsetAsync(h, 0, (size_t)BSZ * UU * sizeof(float));
    cudaMemsetAsync(c, 0, (size_t)BSZ * UU * sizeof(float));

    const int gate_grid = (BSZ * UU + 255) / 256;

    // ---- encoder ----
    // xw[b,t,:] = x[b,t,:] @ enc_W + enc_b  (one big GEMM over B*T rows)
    launch_gemm<0, true, false>(BSZ * TS, GATES, FENC,
                                x, FENC, enc_W, GATES, enc_b,
                                nullptr, 0, xw, GATES);
    for (int t = 0; t < TS; t++) {
        // z = h @ enc_U + xw[:,t,:]
        launch_gemm<0, false, true>(BSZ, GATES, UU,
                                    h, UU, enc_U, GATES, nullptr,
                                    xw + (size_t)t * GATES, TS * GATES,
                                    z, GATES);
        lstm_gates_kernel<<<gate_grid, 256>>>(z, h, c, nullptr, 0);
    }

    // ---- decoder (reuse xw scratch) ----
    launch_gemm<0, true, false>(BSZ * TS, GATES, FDEC,
                                m, FDEC, dec_W, GATES, dec_b,
                                nullptr, 0, xw, GATES);
    for (int t = 0; t < TS; t++) {
        launch_gemm<0, false, true>(BSZ, GATES, UU,
                                    h, UU, dec_U, GATES, nullptr,
                                    xw + (size_t)t * GATES, TS * GATES,
                                    z, GATES);
        lstm_gates_kernel<<<gate_grid, 256>>>(z, h, c, dec, t);
    }

    // ---- MLP head ----
    // t1 = relu(dec @ W_map + b_map)
    launch_gemm<1, true, false>(BSZ, H1, DECFLAT,
                                dec, DECFLAT, W_map, H1, b_map,
                                nullptr, 0, t1, H1);
    // t2 = tanh(t1 @ W1 + b1)
    launch_gemm<2, true, false>(BSZ, H1, H1,
                                t1, H1, W1, H1, b1,
                                nullptr, 0, t2, H1);
    // t1 = tanh(t2 @ W2 + b2)
    launch_gemm<2, true, false>(BSZ, H1, H1,
                                t2, H1, W2, H1, b2,
                                nullptr, 0, t1, H1);
    // t2 = tanh(t1 @ W3 + b3)
    launch_gemm<2, true, false>(BSZ, H1, H1,
                                t1, H1, W3, H1, b3,
                                nullptr, 0, t2, H1);
    // out = t2 @ W_out + b_out
    launch_gemm<0, true, false>(BSZ, OUTN, H1,
                                t2, H1, W_out, OUTN, b_out,
                                nullptr, 0, out, OUTN);
}

// round 3
// speedup vs baseline: 2.2063x; 2.2063x over previous
#include <cuda_runtime.h>
#include <cuda_bf16.h>
#include <cstdint>
#include <math.h>

// ======================= problem dims =======================
#define UU      356
#define GATES   1424
#define BSZ     8192
#define TS      7
#define FENC    69
#define FDEC    45
#define H1      1024
#define OUTN    168

#define HPAD    384
#define XPAD    128
#define MPAD    64
#define DPAD    2496
#define GNPAD   1536
#define ONPAD   256
#define BT      (BSZ*TS)

typedef __nv_bfloat16 bf16;

// ======================= scratch (device globals) =======================
__device__ bf16 g_xhi[(size_t)BT*XPAD],  g_xlo[(size_t)BT*XPAD];
__device__ bf16 g_mhi[(size_t)BT*MPAD],  g_mlo[(size_t)BT*MPAD];
__device__ float g_xw[(size_t)BT*GATES];
__device__ float g_z [(size_t)BSZ*GATES];
__device__ float g_c [(size_t)BSZ*UU];
__device__ bf16 g_hhi[(size_t)BSZ*HPAD], g_hlo[(size_t)BSZ*HPAD];
__device__ bf16 g_dhi[(size_t)BSZ*DPAD], g_dlo[(size_t)BSZ*DPAD];
__device__ bf16 g_t1hi[(size_t)BSZ*H1], g_t1lo[(size_t)BSZ*H1];
__device__ bf16 g_t2hi[(size_t)BSZ*H1], g_t2lo[(size_t)BSZ*H1];
// transposed + split weights, padded [Npad, Kpad]
__device__ bf16 w_encW_hi[(size_t)GNPAD*XPAD], w_encW_lo[(size_t)GNPAD*XPAD];
__device__ bf16 w_decW_hi[(size_t)GNPAD*MPAD], w_decW_lo[(size_t)GNPAD*MPAD];
__device__ bf16 w_encU_hi[(size_t)GNPAD*HPAD], w_encU_lo[(size_t)GNPAD*HPAD];
__device__ bf16 w_decU_hi[(size_t)GNPAD*HPAD], w_decU_lo[(size_t)GNPAD*HPAD];
__device__ bf16 w_map_hi[(size_t)H1*DPAD],     w_map_lo[(size_t)H1*DPAD];
__device__ bf16 w_1_hi[(size_t)H1*H1], w_1_lo[(size_t)H1*H1];
__device__ bf16 w_2_hi[(size_t)H1*H1], w_2_lo[(size_t)H1*H1];
__device__ bf16 w_3_hi[(size_t)H1*H1], w_3_lo[(size_t)H1*H1];
__device__ bf16 w_out_hi[(size_t)ONPAD*H1],    w_out_lo[(size_t)ONPAD*H1];

// ======================= PTX helpers (sm_80-era, no arch-'a' features) ====
__device__ __forceinline__ uint32_t smem_u32(const void* p) {
    uint32_t a;
    asm("{ .reg .u64 t; cvta.to.shared.u64 t, %1; cvt.u32.u64 %0, t; }" : "=r"(a) : "l"(p));
    return a;
}
#define CP_ASYNC16(dst, src) \
    asm volatile("cp.async.cg.shared.global [%0], [%1], 16;" :: "r"(dst), "l"(src))
#define CP_COMMIT()  asm volatile("cp.async.commit_group;" ::: "memory")
#define CP_WAIT0()   asm volatile("cp.async.wait_group 0;" ::: "memory")
#define LDSM4(r0,r1,r2,r3,addr) \
    asm volatile("ldmatrix.sync.aligned.m8n8.x4.shared.b16 {%0,%1,%2,%3}, [%4];" \
        : "=r"(r0),"=r"(r1),"=r"(r2),"=r"(r3) : "r"(addr))

__device__ __forceinline__ void mma16816(float* d, const uint32_t* a, const uint32_t* b) {
    asm volatile("mma.sync.aligned.m16n8k16.row.col.f32.bf16.bf16.f32 "
        "{%0,%1,%2,%3}, {%4,%5,%6,%7}, {%8,%9}, {%0,%1,%2,%3};"
        : "+f"(d[0]), "+f"(d[1]), "+f"(d[2]), "+f"(d[3])
        : "r"(a[0]), "r"(a[1]), "r"(a[2]), "r"(a[3]), "r"(b[0]), "r"(b[1]));
}

__device__ __forceinline__ void split2(float v, bf16& hi, bf16& lo) {
    hi = __float2bfloat16(v);
    lo = __float2bfloat16(v - __bfloat162float(hi));
}

// ======================= HMMA GEMM =======================
// C[M,N] = act( A @ B^T (+Ci) (+bias) )
// A:[M,Kpad] hi/lo bf16 row-major; B:[Npad,Kpad] hi/lo bf16 row-major.
// CTA tile 128x128, BK=32, 8 warps (4 in M x 2 in N), warp tile 32x64.
// Smem rows padded to 80B -> conflict-free ldmatrix.
#define ROWB   80
#define TILEB  (128*ROWB)        // 10240 per operand tile
#define STAGE  (4*TILEB)         // Ahi,Alo,Bhi,Blo = 40960
#define SMEM_BYTES (2*STAGE)     // 81920

template<int ACT, bool BIAS, bool CINIT, bool WF32, bool WSPLIT>
__global__ __launch_bounds__(256)
void mma_gemm(int M, int N, int Kpad,
              const bf16* __restrict__ Ahi, const bf16* __restrict__ Alo,
              const bf16* __restrict__ Bhi, const bf16* __restrict__ Blo,
              const float* __restrict__ bias,
              const float* __restrict__ Ci, int ldci,
              float* __restrict__ Cf, int ldc,
              bf16* __restrict__ Chi, bf16* __restrict__ Clo, int ldcs)
{
    extern __shared__ char smem[];
    const uint32_t sbase = smem_u32(smem);
    const int tid  = threadIdx.x;
    const int lane = tid & 31;
    const int wid  = tid >> 5;
    const int warp_m = wid & 3;          // 4 warps in M: 32 rows each
    const int warp_n = wid >> 2;         // 2 warps in N: 64 cols each
    const int bm = blockIdx.y * 128;
    const int bn = blockIdx.x * 128;

    const int ld = Kpad * 2;             // bytes per row of all operands
    const char* gAhi = (const char*)Ahi + (size_t)bm * ld;
    const char* gAlo = (const char*)Alo + (size_t)bm * ld;
    const char* gBhi = (const char*)Bhi + (size_t)bn * ld;
    const char* gBlo = (const char*)Blo + (size_t)bn * ld;

    // per-thread staging coords: 2 x (row, 16B-seg) covering 128x64B
    const int r0 = tid >> 2,        s0 = (tid & 3) * 16;
    const int r1 = (tid + 256) >> 2, s1 = s0;

    float acc[2][8][4];
    #pragma unroll
    for (int i = 0; i < 2; i++)
        #pragma unroll
        for (int j = 0; j < 8; j++)
            #pragma unroll
            for (int q = 0; q < 4; q++) acc[i][j][q] = 0.f;

    const int NC = Kpad >> 5;

    // ---- stage chunk 0 ----
    {
        uint32_t s = sbase;
        CP_ASYNC16(s + 0*TILEB + r0*ROWB + s0, gAhi + (size_t)r0*ld + s0);
        CP_ASYNC16(s + 0*TILEB + r1*ROWB + s1, gAhi + (size_t)r1*ld + s1);
        CP_ASYNC16(s + 1*TILEB + r0*ROWB + s0, gAlo + (size_t)r0*ld + s0);
        CP_ASYNC16(s + 1*TILEB + r1*ROWB + s1, gAlo + (size_t)r1*ld + s1);
        CP_ASYNC16(s + 2*TILEB + r0*ROWB + s0, gBhi + (size_t)r0*ld + s0);
        CP_ASYNC16(s + 2*TILEB + r1*ROWB + s1, gBhi + (size_t)r1*ld + s1);
        CP_ASYNC16(s + 3*TILEB + r0*ROWB + s0, gBlo + (size_t)r0*ld + s0);
        CP_ASYNC16(s + 3*TILEB + r1*ROWB + s1, gBlo + (size_t)r1*ld + s1);
        CP_COMMIT();
    }

    // precomputed ldmatrix intra-tile offsets
    const uint32_t aoff = (uint32_t)((warp_m*32 + (lane & 15)) * ROWB + (lane >> 4) * 16);
    const uint32_t boff = (uint32_t)((warp_n*64 + (lane >> 4)*8 + (lane & 7)) * ROWB
                                     + ((lane >> 3) & 1) * 16);

    for (int c = 0; c < NC; c++) {
        CP_WAIT0();
        __syncthreads();
        if (c + 1 < NC) {
            uint32_t s = sbase + ((c + 1) & 1) * STAGE;
            int ko = (c + 1) << 6;       // byte offset into K
            CP_ASYNC16(s + 0*TILEB + r0*ROWB + s0, gAhi + (size_t)r0*ld + ko + s0);
            CP_ASYNC16(s + 0*TILEB + r1*ROWB + s1, gAhi + (size_t)r1*ld + ko + s1);
            CP_ASYNC16(s + 1*TILEB + r0*ROWB + s0, gAlo + (size_t)r0*ld + ko + s0);
            CP_ASYNC16(s + 1*TILEB + r1*ROWB + s1, gAlo + (size_t)r1*ld + ko + s1);
            CP_ASYNC16(s + 2*TILEB + r0*ROWB + s0, gBhi + (size_t)r0*ld + ko + s0);
            CP_ASYNC16(s + 2*TILEB + r1*ROWB + s1, gBhi + (size_t)r1*ld + ko + s1);
            CP_ASYNC16(s + 3*TILEB + r0*ROWB + s0, gBlo + (size_t)r0*ld + ko + s0);
            CP_ASYNC16(s + 3*TILEB + r1*ROWB + s1, gBlo + (size_t)r1*ld + ko + s1);
            CP_COMMIT();
        }

        const uint32_t sb = sbase + (c & 1) * STAGE;
        #pragma unroll
        for (int kk = 0; kk < 2; kk++) {
            const uint32_t kb = kk * 32;
            uint32_t ahi[2][4], alo[2][4], bhi[4][4], blo[4][4];
            #pragma unroll
            for (int mi = 0; mi < 2; mi++) {
                uint32_t a = sb + aoff + mi * (16 * ROWB) + kb;
                LDSM4(ahi[mi][0], ahi[mi][1], ahi[mi][2], ahi[mi][3], a + 0*TILEB);
                LDSM4(alo[mi][0], alo[mi][1], alo[mi][2], alo[mi][3], a + 1*TILEB);
            }
            #pragma unroll
            for (int g = 0; g < 4; g++) {
                uint32_t b = sb + boff + g * (16 * ROWB) + kb;
                LDSM4(bhi[g][0], bhi[g][1], bhi[g][2], bhi[g][3], b + 2*TILEB);
                LDSM4(blo[g][0], blo[g][1], blo[g][2], blo[g][3], b + 3*TILEB);
            }
            #pragma unroll
            for (int mi = 0; mi < 2; mi++)
                #pragma unroll
                for (int nj = 0; nj < 8; nj++) {
                    const uint32_t* bh = &bhi[nj >> 1][(nj & 1) * 2];
                    const uint32_t* bl = &blo[nj >> 1][(nj & 1) * 2];
                    mma16816(acc[mi][nj], ahi[mi], bh);
                    mma16816(acc[mi][nj], ahi[mi], bl);
                    mma16816(acc[mi][nj], alo[mi], bh);
                }
        }
        __syncthreads();
    }

    // ---- epilogue: registers -> global ----
    const int tr = lane >> 2;
    const int tc = (lane & 3) * 2;
    const int row0 = bm + warp_m * 32;
    const int col0 = bn + warp_n * 64;
    #pragma unroll
    for (int mi = 0; mi < 2; mi++)
        #pragma unroll
        for (int nj = 0; nj < 8; nj++) {
            int gc = col0 + nj * 8 + tc;
            if (gc >= N) continue;
            float b0 = 0.f, b1 = 0.f;
            if (BIAS) { b0 = bias[gc]; b1 = bias[gc + 1]; }
            #pragma unroll
            for (int hh = 0; hh < 2; hh++) {
                int gr = row0 + mi * 16 + hh * 8 + tr;
                float v0 = acc[mi][nj][hh * 2 + 0];
                float v1 = acc[mi][nj][hh * 2 + 1];
                if (CINIT) {
                    const float* ci = Ci + (size_t)gr * ldci + gc;
                    v0 += ci[0]; v1 += ci[1];
                }
                if (BIAS) { v0 += b0; v1 += b1; }
                if (ACT == 1) { v0 = fmaxf(v0, 0.f); v1 = fmaxf(v1, 0.f); }
                else if (ACT == 2) { v0 = tanhf(v0); v1 = tanhf(v1); }
                if (WF32) {
                    float2* p = (float2*)(Cf + (size_t)gr * ldc + gc);
                    *p = make_float2(v0, v1);
                }
                if (WSPLIT) {
                    bf16 h0, l0, h1, l1;
                    split2(v0, h0, l0); split2(v1, h1, l1);
                    *(__nv_bfloat162*)(Chi + (size_t)gr * ldcs + gc) =
                        __nv_bfloat162(h0, h1);
                    *(__nv_bfloat162*)(Clo + (size_t)gr * ldcs + gc) =
                        __nv_bfloat162(l0, l1);
                }
            }
        }
}

// ======================= prep kernels =======================
__global__ void prep_weight(const float* __restrict__ W, int K, int N, int Kpad, int total,
                            bf16* __restrict__ Whi, bf16* __restrict__ Wlo)
{
    int idx = blockIdx.x * blockDim.x + threadIdx.x;
    if (idx >= total) return;
    int n = idx / Kpad, k = idx - n * Kpad;
    float v = (k < K && n < N) ? W[(size_t)k * N + n] : 0.f;
    bf16 hi, lo; split2(v, hi, lo);
    Whi[idx] = hi; Wlo[idx] = lo;
}

__global__ void prep_act(const float* __restrict__ X, int total, int K, int Kpad,
                         bf16* __restrict__ Ahi, bf16* __restrict__ Alo)
{
    int idx = blockIdx.x * blockDim.x + threadIdx.x;
    if (idx >= total) return;
    int r = idx / Kpad, k = idx - r * Kpad;
    float v = (k < K) ? X[(size_t)r * K + k] : 0.f;
    bf16 hi, lo; split2(v, hi, lo);
    Ahi[idx] = hi; Alo[idx] = lo;
}

// ======================= LSTM gates =======================
__global__ void lstm_gates(const float* __restrict__ z, float* __restrict__ c,
                           bf16* __restrict__ hhi, bf16* __restrict__ hlo,
                           bf16* __restrict__ dhi, bf16* __restrict__ dlo, int t)
{
    int idx = blockIdx.x * blockDim.x + threadIdx.x;
    if (idx >= BSZ * UU) return;
    int b = idx / UU, j = idx - b * UU;
    const float* zr = z + (size_t)b * GATES;
    float zi = zr[j], zf = zr[UU + j], zg = zr[2 * UU + j], zo = zr[3 * UU + j];
    float ig = 1.f / (1.f + expf(-zi));
    float fg = 1.f / (1.f + expf(-zf));
    float gg = tanhf(zg);
    float og = 1.f / (1.f + expf(-zo));
    float cn = fg * c[idx] + ig * gg;
    c[idx] = cn;
    float hn = og * tanhf(cn);
    bf16 hi, lo; split2(hn, hi, lo);
    hhi[(size_t)b * HPAD + j] = hi;
    hlo[(size_t)b * HPAD + j] = lo;
    if (dhi) {
        dhi[(size_t)b * DPAD + t * UU + j] = hi;
        dlo[(size_t)b * DPAD + t * UU + j] = lo;
    }
}

// ======================= host side =======================
template<int ACT, bool BIAS, bool CINIT, bool WF32, bool WSPLIT>
static inline void launch_mma(int M, int N, int Kpad,
                              const bf16* Ahi, const bf16* Alo,
                              const bf16* Bhi, const bf16* Blo,
                              const float* bias, const float* Ci, int ldci,
                              float* Cf, int ldc, bf16* Chi, bf16* Clo, int ldcs)
{
    dim3 grid((N + 127) / 128, M / 128);
    mma_gemm<ACT, BIAS, CINIT, WF32, WSPLIT><<<grid, 256, SMEM_BYTES>>>(
        M, N, Kpad, Ahi, Alo, Bhi, Blo, bias, Ci, ldci, Cf, ldc, Chi, Clo, ldcs);
}

static inline void set_attrs() {
    cudaFuncSetAttribute(mma_gemm<0, true,  false, true,  false>, cudaFuncAttributeMaxDynamicSharedMemorySize, SMEM_BYTES);
    cudaFuncSetAttribute(mma_gemm<0, false, true,  true,  false>, cudaFuncAttributeMaxDynamicSharedMemorySize, SMEM_BYTES);
    cudaFuncSetAttribute(mma_gemm<1, true,  false, false, true >, cudaFuncAttributeMaxDynamicSharedMemorySize, SMEM_BYTES);
    cudaFuncSetAttribute(mma_gemm<2, true,  false, false, true >, cudaFuncAttributeMaxDynamicSharedMemorySize, SMEM_BYTES);
}

extern "C" void kernel_launch(void* const* d_in, const int* /*in_sizes*/, int /*n_in*/,
                              void* d_out, int /*out_size*/)
{
    const float* x     = (const float*)d_in[0];
    const float* m     = (const float*)d_in[1];
    const float* enc_W = (const float*)d_in[2];
    const float* enc_U = (const float*)d_in[3];
    const float* enc_b = (const float*)d_in[4];
    const float* dec_W = (const float*)d_in[5];
    const float* dec_U = (const float*)d_in[6];
    const float* dec_b = (const float*)d_in[7];
    const float* W_map = (const float*)d_in[8];
    const float* b_map = (const float*)d_in[9];
    const float* W1    = (const float*)d_in[10];
    const float* b1    = (const float*)d_in[11];
    const float* W2    = (const float*)d_in[12];
    const float* b2    = (const float*)d_in[13];
    const float* W3    = (const float*)d_in[14];
    const float* b3    = (const float*)d_in[15];
    const float* W_out = (const float*)d_in[16];
    const float* b_out = (const float*)d_in[17];
    float* out = (float*)d_out;

    set_attrs();

    bf16 *xhi,*xlo,*mhi,*mlo,*hhi,*hlo,*dhi,*dlo,*t1hi,*t1lo,*t2hi,*t2lo;
    bf16 *eWh,*eWl,*dWh,*dWl,*eUh,*eUl,*dUh,*dUl,*wmh,*wml,*w1h,*w1l,*w2h,*w2l,*w3h,*w3l,*woh,*wol;
    float *xw,*z,*c;
    cudaGetSymbolAddress((void**)&xhi, g_xhi);  cudaGetSymbolAddress((void**)&xlo, g_xlo);
    cudaGetSymbolAddress((void**)&mhi, g_mhi);  cudaGetSymbolAddress((void**)&mlo, g_mlo);
    cudaGetSymbolAddress((void**)&hhi, g_hhi);  cudaGetSymbolAddress((void**)&hlo, g_hlo);
    cudaGetSymbolAddress((void**)&dhi, g_dhi);  cudaGetSymbolAddress((void**)&dlo, g_dlo);
    cudaGetSymbolAddress((void**)&t1hi, g_t1hi); cudaGetSymbolAddress((void**)&t1lo, g_t1lo);
    cudaGetSymbolAddress((void**)&t2hi, g_t2hi); cudaGetSymbolAddress((void**)&t2lo, g_t2lo);
    cudaGetSymbolAddress((void**)&eWh, w_encW_hi); cudaGetSymbolAddress((void**)&eWl, w_encW_lo);
    cudaGetSymbolAddress((void**)&dWh, w_decW_hi); cudaGetSymbolAddress((void**)&dWl, w_decW_lo);
    cudaGetSymbolAddress((void**)&eUh, w_encU_hi); cudaGetSymbolAddress((void**)&eUl, w_encU_lo);
    cudaGetSymbolAddress((void**)&dUh, w_decU_hi); cudaGetSymbolAddress((void**)&dUl, w_decU_lo);
    cudaGetSymbolAddress((void**)&wmh, w_map_hi);  cudaGetSymbolAddress((void**)&wml, w_map_lo);
    cudaGetSymbolAddress((void**)&w1h, w_1_hi);    cudaGetSymbolAddress((void**)&w1l, w_1_lo);
    cudaGetSymbolAddress((void**)&w2h, w_2_hi);    cudaGetSymbolAddress((void**)&w2l, w_2_lo);
    cudaGetSymbolAddress((void**)&w3h, w_3_hi);    cudaGetSymbolAddress((void**)&w3l, w_3_lo);
    cudaGetSymbolAddress((void**)&woh, w_out_hi);  cudaGetSymbolAddress((void**)&wol, w_out_lo);
    cudaGetSymbolAddress((void**)&xw, g_xw);
    cudaGetSymbolAddress((void**)&z,  g_z);
    cudaGetSymbolAddress((void**)&c,  g_c);

    // init states + padding tails
    cudaMemsetAsync(c,   0, (size_t)BSZ * UU * sizeof(float));
    cudaMemsetAsync(hhi, 0, (size_t)BSZ * HPAD * sizeof(bf16));
    cudaMemsetAsync(hlo, 0, (size_t)BSZ * HPAD * sizeof(bf16));
    cudaMemsetAsync(dhi, 0, (size_t)BSZ * DPAD * sizeof(bf16));
    cudaMemsetAsync(dlo, 0, (size_t)BSZ * DPAD * sizeof(bf16));

    // weight prep (transpose + hi/lo split, padded)
    auto pw = [](const float* W, int K, int N, int Kpad, int Npad, bf16* hi, bf16* lo) {
        int total = Npad * Kpad;
        prep_weight<<<(total + 255) / 256, 256>>>(W, K, N, Kpad, total, hi, lo);
    };
    pw(enc_W, FENC, GATES, XPAD, GNPAD, eWh, eWl);
    pw(dec_W, FDEC, GATES, MPAD, GNPAD, dWh, dWl);
    pw(enc_U, UU,   GATES, HPAD, GNPAD, eUh, eUl);
    pw(dec_U, UU,   GATES, HPAD, GNPAD, dUh, dUl);
    pw(W_map, TS*UU, H1, DPAD, H1, wmh, wml);
    pw(W1, H1, H1, H1, H1, w1h, w1l);
    pw(W2, H1, H1, H1, H1, w2h, w2l);
    pw(W3, H1, H1, H1, H1, w3h, w3l);
    pw(W_out, H1, OUTN, H1, ONPAD, woh, wol);

    // activation prep
    {
        int tot = BT * XPAD;
        prep_act<<<(tot + 255) / 256, 256>>>(x, tot, FENC, XPAD, xhi, xlo);
        tot = BT * MPAD;
        prep_act<<<(tot + 255) / 256, 256>>>(m, tot, FDEC, MPAD, mhi, mlo);
    }

    const int gate_grid = (BSZ * UU + 255) / 256;

    // encoder input projection: xw = x @ enc_W + enc_b
    launch_mma<0, true, false, true, false>(BT, GATES, XPAD, xhi, xlo, eWh, eWl,
                                            enc_b, nullptr, 0, xw, GATES, nullptr, nullptr, 0);
    for (int t = 0; t < TS; t++) {
        launch_mma<0, false, true, true, false>(BSZ, GATES, HPAD, hhi, hlo, eUh, eUl,
                                                nullptr, xw + (size_t)t * GATES, TS * GATES,
                                                z, GATES, nullptr, nullptr, 0);
        lstm_gates<<<gate_grid, 256>>>(z, c, hhi, hlo, nullptr, nullptr, 0);
    }

    // decoder input projection (reuse xw)
    launch_mma<0, true, false, true, false>(BT, GATES, MPAD, mhi, mlo, dWh, dWl,
                                            dec_b, nullptr, 0, xw, GATES, nullptr, nullptr, 0);
    for (int t = 0; t < TS; t++) {
        launch_mma<0, false, true, true, false>(BSZ, GATES, HPAD, hhi, hlo, dUh, dUl,
                                                nullptr, xw + (size_t)t * GATES, TS * GATES,
                                                z, GATES, nullptr, nullptr, 0);
        lstm_gates<<<gate_grid, 256>>>(z, c, hhi, hlo, dhi, dlo, t);
    }

    // MLP head
    launch_mma<1, true, false, false, true>(BSZ, H1, DPAD, dhi, dlo, wmh, wml,
                                            b_map, nullptr, 0, nullptr, 0, t1hi, t1lo, H1);
    launch_mma<2, true, false, false, true>(BSZ, H1, H1, t1hi, t1lo, w1h, w1l,
                                            b1, nullptr, 0, nullptr, 0, t2hi, t2lo, H1);
    launch_mma<2, true, false, false, true>(BSZ, H1, H1, t2hi, t2lo, w2h, w2l,
                                            b2, nullptr, 0, nullptr, 0, t1hi, t1lo, H1);
    launch_mma<2, true, false, false, true>(BSZ, H1, H1, t1hi, t1lo, w3h, w3l,
                                            b3, nullptr, 0, nullptr, 0, t2hi, t2lo, H1);
    launch_mma<0, true, false, true, false>(BSZ, OUTN, H1, t2hi, t2lo, woh, wol,
                                            b_out, nullptr, 0, out, OUTN, nullptr, nullptr, 0);
}

// round 4
// speedup vs baseline: 2.3745x; 1.0762x over previous
#include <cuda_runtime.h>
#include <cuda_bf16.h>
#include <cstdint>
#include <math.h>

// ======================= problem dims =======================
#define UU      356
#define GATES   1424
#define BSZ     8192
#define TS      7
#define FENC    69
#define FDEC    45
#define H1      1024
#define OUTN    168

#define HPAD    384
#define XPAD    128
#define MPAD    64
#define DPAD    2496
#define GNPAD   1536
#define ONPAD   256
#define BT      (BSZ*TS)

typedef __nv_bfloat16 bf16;

// ======================= scratch (device globals) =======================
__device__ bf16 g_xhi[(size_t)BT*XPAD],  g_xlo[(size_t)BT*XPAD];
__device__ bf16 g_mhi[(size_t)BT*MPAD],  g_mlo[(size_t)BT*MPAD];
__device__ float g_xw[(size_t)BT*GATES];
__device__ float g_z [(size_t)BSZ*GATES];
__device__ float g_c [(size_t)BSZ*UU];
__device__ bf16 g_hhi[(size_t)BSZ*HPAD], g_hlo[(size_t)BSZ*HPAD];
__device__ bf16 g_dhi[(size_t)BSZ*DPAD], g_dlo[(size_t)BSZ*DPAD];
__device__ bf16 g_t1hi[(size_t)BSZ*H1], g_t1lo[(size_t)BSZ*H1];
__device__ bf16 g_t2hi[(size_t)BSZ*H1], g_t2lo[(size_t)BSZ*H1];
// transposed + split weights, padded [Npad, Kpad]
__device__ bf16 w_encW_hi[(size_t)GNPAD*XPAD], w_encW_lo[(size_t)GNPAD*XPAD];
__device__ bf16 w_decW_hi[(size_t)GNPAD*MPAD], w_decW_lo[(size_t)GNPAD*MPAD];
__device__ bf16 w_encU_hi[(size_t)GNPAD*HPAD], w_encU_lo[(size_t)GNPAD*HPAD];
__device__ bf16 w_decU_hi[(size_t)GNPAD*HPAD], w_decU_lo[(size_t)GNPAD*HPAD];
__device__ bf16 w_map_hi[(size_t)H1*DPAD],     w_map_lo[(size_t)H1*DPAD];
__device__ bf16 w_1_hi[(size_t)H1*H1], w_1_lo[(size_t)H1*H1];
__device__ bf16 w_2_hi[(size_t)H1*H1], w_2_lo[(size_t)H1*H1];
__device__ bf16 w_3_hi[(size_t)H1*H1], w_3_lo[(size_t)H1*H1];
__device__ bf16 w_out_hi[(size_t)ONPAD*H1],    w_out_lo[(size_t)ONPAD*H1];

// ======================= PTX helpers (sm_80-era) =======================
__device__ __forceinline__ uint32_t smem_u32(const void* p) {
    uint32_t a;
    asm("{ .reg .u64 t; cvta.to.shared.u64 t, %1; cvt.u32.u64 %0, t; }" : "=r"(a) : "l"(p));
    return a;
}
#define CP_ASYNC16(dst, src) \
    asm volatile("cp.async.cg.shared.global [%0], [%1], 16;" :: "r"(dst), "l"(src))
#define CP_COMMIT()  asm volatile("cp.async.commit_group;" ::: "memory")
#define CP_WAIT1()   asm volatile("cp.async.wait_group 1;" ::: "memory")
#define LDSM4(r0,r1,r2,r3,addr) \
    asm volatile("ldmatrix.sync.aligned.m8n8.x4.shared.b16 {%0,%1,%2,%3}, [%4];" \
        : "=r"(r0),"=r"(r1),"=r"(r2),"=r"(r3) : "r"(addr))

__device__ __forceinline__ void mma16816(float* d, const uint32_t* a, const uint32_t* b) {
    asm volatile("mma.sync.aligned.m16n8k16.row.col.f32.bf16.bf16.f32 "
        "{%0,%1,%2,%3}, {%4,%5,%6,%7}, {%8,%9}, {%0,%1,%2,%3};"
        : "+f"(d[0]), "+f"(d[1]), "+f"(d[2]), "+f"(d[3])
        : "r"(a[0]), "r"(a[1]), "r"(a[2]), "r"(a[3]), "r"(b[0]), "r"(b[1]));
}

__device__ __forceinline__ void split2(float v, bf16& hi, bf16& lo) {
    hi = __float2bfloat16(v);
    lo = __float2bfloat16(v - __bfloat162float(hi));
}

// ======================= HMMA GEMM =======================
// C[M,N] = act( A @ B^T (+Ci) (+bias) )
// CTA tile 256x128, BK=32, 8 warps (4 in M x 2 in N), warp tile 64x64.
// 3-stage cp.async pipeline. Smem rows padded to 80B -> conflict-free ldmatrix.
#define ROWB    80
#define A_TILEB (256*ROWB)                 // 20480 per A split
#define B_TILEB (128*ROWB)                 // 10240 per B split
#define STAGE   (2*A_TILEB + 2*B_TILEB)    // 61440
#define NSTAGE  3
#define SMEM_BYTES (NSTAGE*STAGE)          // 184320

template<int ACT, bool BIAS, bool CINIT, bool WF32, bool WSPLIT>
__global__ __launch_bounds__(256)
void mma_gemm(int M, int N, int Kpad,
              const bf16* __restrict__ Ahi, const bf16* __restrict__ Alo,
              const bf16* __restrict__ Bhi, const bf16* __restrict__ Blo,
              const float* __restrict__ bias,
              const float* __restrict__ Ci, int ldci,
              float* __restrict__ Cf, int ldc,
              bf16* __restrict__ Chi, bf16* __restrict__ Clo, int ldcs)
{
    extern __shared__ char smem[];
    const uint32_t sbase = smem_u32(smem);
    const int tid  = threadIdx.x;
    const int lane = tid & 31;
    const int wid  = tid >> 5;
    const int warp_m = wid & 3;          // 4 warps in M: 64 rows each
    const int warp_n = wid >> 2;         // 2 warps in N: 64 cols each
    const int bm = blockIdx.y * 256;
    const int bn = blockIdx.x * 128;

    const int ld = Kpad * 2;
    const char* gAhi = (const char*)Ahi + (size_t)bm * ld;
    const char* gAlo = (const char*)Alo + (size_t)bm * ld;
    const char* gBhi = (const char*)Bhi + (size_t)bn * ld;
    const char* gBlo = (const char*)Blo + (size_t)bn * ld;

    const int rr  = tid >> 2;            // 0..63
    const int seg = (tid & 3) * 16;      // 16B segment within 64B k-chunk

    float acc[4][8][4];
    #pragma unroll
    for (int i = 0; i < 4; i++)
        #pragma unroll
        for (int j = 0; j < 8; j++)
            #pragma unroll
            for (int q = 0; q < 4; q++) acc[i][j][q] = 0.f;

    const int NC = Kpad >> 5;

    // stage loader: 12 cp.asyncs per thread per stage
    auto stage_load = [&](int c) {
        uint32_t s = sbase + (c % NSTAGE) * STAGE;
        int ko = c << 6;                 // 32 k * 2B
        #pragma unroll
        for (int i = 0; i < 4; i++) {
            int r = rr + i * 64;
            CP_ASYNC16(s + 0*A_TILEB + r*ROWB + seg, gAhi + (size_t)r*ld + ko + seg);
            CP_ASYNC16(s + 1*A_TILEB + r*ROWB + seg, gAlo + (size_t)r*ld + ko + seg);
        }
        #pragma unroll
        for (int i = 0; i < 2; i++) {
            int r = rr + i * 64;
            CP_ASYNC16(s + 2*A_TILEB + 0*B_TILEB + r*ROWB + seg, gBhi + (size_t)r*ld + ko + seg);
            CP_ASYNC16(s + 2*A_TILEB + 1*B_TILEB + r*ROWB + seg, gBlo + (size_t)r*ld + ko + seg);
        }
    };

    stage_load(0); CP_COMMIT();
    if (NC > 1) { stage_load(1); }
    CP_COMMIT();

    const uint32_t aoff = (uint32_t)((warp_m*64 + (lane & 15)) * ROWB + (lane >> 4) * 16);
    const uint32_t boff = (uint32_t)((warp_n*64 + (lane >> 4)*8 + (lane & 7)) * ROWB
                                     + ((lane >> 3) & 1) * 16);

    for (int c = 0; c < NC; c++) {
        CP_WAIT1();
        __syncthreads();
        if (c + 2 < NC) stage_load(c + 2);
        CP_COMMIT();                      // empty commit at tail keeps wait_group(1) valid

        const uint32_t sb = sbase + (c % NSTAGE) * STAGE;
        const uint32_t sa0 = sb;                 // Ahi
        const uint32_t sa1 = sb + A_TILEB;       // Alo
        const uint32_t sb0 = sb + 2*A_TILEB;     // Bhi
        const uint32_t sb1 = sb0 + B_TILEB;      // Blo

        #pragma unroll
        for (int kk = 0; kk < 2; kk++) {
            const uint32_t kb = kk * 32;
            uint32_t ahi[4][4], alo[4][4], bhi[4][4], blo[4][4];
            #pragma unroll
            for (int mi = 0; mi < 4; mi++) {
                uint32_t a = aoff + mi * (16 * ROWB) + kb;
                LDSM4(ahi[mi][0], ahi[mi][1], ahi[mi][2], ahi[mi][3], sa0 + a);
                LDSM4(alo[mi][0], alo[mi][1], alo[mi][2], alo[mi][3], sa1 + a);
            }
            #pragma unroll
            for (int g = 0; g < 4; g++) {
                uint32_t b = boff + g * (16 * ROWB) + kb;
                LDSM4(bhi[g][0], bhi[g][1], bhi[g][2], bhi[g][3], sb0 + b);
                LDSM4(blo[g][0], blo[g][1], blo[g][2], blo[g][3], sb1 + b);
            }
            #pragma unroll
            for (int mi = 0; mi < 4; mi++)
                #pragma unroll
                for (int nj = 0; nj < 8; nj++) {
                    const uint32_t* bh = &bhi[nj >> 1][(nj & 1) * 2];
                    const uint32_t* bl = &blo[nj >> 1][(nj & 1) * 2];
                    mma16816(acc[mi][nj], ahi[mi], bh);
                    mma16816(acc[mi][nj], ahi[mi], bl);
                    mma16816(acc[mi][nj], alo[mi], bh);
                }
        }
        __syncthreads();
    }

    // ---- epilogue: registers -> global ----
    const int tr = lane >> 2;
    const int tc = (lane & 3) * 2;
    const int row0 = bm + warp_m * 64;
    const int col0 = bn + warp_n * 64;
    #pragma unroll
    for (int mi = 0; mi < 4; mi++)
        #pragma unroll
        for (int nj = 0; nj < 8; nj++) {
            int gc = col0 + nj * 8 + tc;
            if (gc >= N) continue;
            float b0 = 0.f, b1 = 0.f;
            if (BIAS) { b0 = bias[gc]; b1 = bias[gc + 1]; }
            #pragma unroll
            for (int hh = 0; hh < 2; hh++) {
                int gr = row0 + mi * 16 + hh * 8 + tr;
                float v0 = acc[mi][nj][hh * 2 + 0];
                float v1 = acc[mi][nj][hh * 2 + 1];
                if (CINIT) {
                    const float* ci = Ci + (size_t)gr * ldci + gc;
                    v0 += ci[0]; v1 += ci[1];
                }
                if (BIAS) { v0 += b0; v1 += b1; }
                if (ACT == 1) { v0 = fmaxf(v0, 0.f); v1 = fmaxf(v1, 0.f); }
                else if (ACT == 2) { v0 = tanhf(v0); v1 = tanhf(v1); }
                if (WF32) {
                    float2* p = (float2*)(Cf + (size_t)gr * ldc + gc);
                    *p = make_float2(v0, v1);
                }
                if (WSPLIT) {
                    bf16 h0, l0, h1, l1;
                    split2(v0, h0, l0); split2(v1, h1, l1);
                    *(__nv_bfloat162*)(Chi + (size_t)gr * ldcs + gc) =
                        __nv_bfloat162(h0, h1);
                    *(__nv_bfloat162*)(Clo + (size_t)gr * ldcs + gc) =
                        __nv_bfloat162(l0, l1);
                }
            }
        }
}

// ======================= prep kernels =======================
__global__ void prep_weight(const float* __restrict__ W, int K, int N, int Kpad, int total,
                            bf16* __restrict__ Whi, bf16* __restrict__ Wlo)
{
    int idx = blockIdx.x * blockDim.x + threadIdx.x;
    if (idx >= total) return;
    int n = idx / Kpad, k = idx - n * Kpad;
    float v = (k < K && n < N) ? W[(size_t)k * N + n] : 0.f;
    bf16 hi, lo; split2(v, hi, lo);
    Whi[idx] = hi; Wlo[idx] = lo;
}

__global__ void prep_act(const float* __restrict__ X, int total, int K, int Kpad,
                         bf16* __restrict__ Ahi, bf16* __restrict__ Alo)
{
    int idx = blockIdx.x * blockDim.x + threadIdx.x;
    if (idx >= total) return;
    int r = idx / Kpad, k = idx - r * Kpad;
    float v = (k < K) ? X[(size_t)r * K + k] : 0.f;
    bf16 hi, lo; split2(v, hi, lo);
    Ahi[idx] = hi; Alo[idx] = lo;
}

// ======================= LSTM gates =======================
__global__ void lstm_gates(const float* __restrict__ z, float* __restrict__ c,
                           bf16* __restrict__ hhi, bf16* __restrict__ hlo,
                           bf16* __restrict__ dhi, bf16* __restrict__ dlo, int t)
{
    int idx = blockIdx.x * blockDim.x + threadIdx.x;
    if (idx >= BSZ * UU) return;
    int b = idx / UU, j = idx - b * UU;
    const float* zr = z + (size_t)b * GATES;
    float zi = zr[j], zf = zr[UU + j], zg = zr[2 * UU + j], zo = zr[3 * UU + j];
    float ig = 1.f / (1.f + expf(-zi));
    float fg = 1.f / (1.f + expf(-zf));
    float gg = tanhf(zg);
    float og = 1.f / (1.f + expf(-zo));
    float cn = fg * c[idx] + ig * gg;
    c[idx] = cn;
    float hn = og * tanhf(cn);
    bf16 hi, lo; split2(hn, hi, lo);
    hhi[(size_t)b * HPAD + j] = hi;
    hlo[(size_t)b * HPAD + j] = lo;
    if (dhi) {
        dhi[(size_t)b * DPAD + t * UU + j] = hi;
        dlo[(size_t)b * DPAD + t * UU + j] = lo;
    }
}

// ======================= host side =======================
template<int ACT, bool BIAS, bool CINIT, bool WF32, bool WSPLIT>
static inline void launch_mma(int M, int N, int Kpad,
                              const bf16* Ahi, const bf16* Alo,
                              const bf16* Bhi, const bf16* Blo,
                              const float* bias, const float* Ci, int ldci,
                              float* Cf, int ldc, bf16* Chi, bf16* Clo, int ldcs)
{
    dim3 grid((N + 127) / 128, M / 256);
    mma_gemm<ACT, BIAS, CINIT, WF32, WSPLIT><<<grid, 256, SMEM_BYTES>>>(
        M, N, Kpad, Ahi, Alo, Bhi, Blo, bias, Ci, ldci, Cf, ldc, Chi, Clo, ldcs);
}

static inline void set_attrs() {
    cudaFuncSetAttribute(mma_gemm<0, true,  false, true,  false>, cudaFuncAttributeMaxDynamicSharedMemorySize, SMEM_BYTES);
    cudaFuncSetAttribute(mma_gemm<0, false, true,  true,  false>, cudaFuncAttributeMaxDynamicSharedMemorySize, SMEM_BYTES);
    cudaFuncSetAttribute(mma_gemm<1, true,  false, false, true >, cudaFuncAttributeMaxDynamicSharedMemorySize, SMEM_BYTES);
    cudaFuncSetAttribute(mma_gemm<2, true,  false, false, true >, cudaFuncAttributeMaxDynamicSharedMemorySize, SMEM_BYTES);
}

extern "C" void kernel_launch(void* const* d_in, const int* /*in_sizes*/, int /*n_in*/,
                              void* d_out, int /*out_size*/)
{
    const float* x     = (const float*)d_in[0];
    const float* m     = (const float*)d_in[1];
    const float* enc_W = (const float*)d_in[2];
    const float* enc_U = (const float*)d_in[3];
    const float* enc_b = (const float*)d_in[4];
    const float* dec_W = (const float*)d_in[5];
    const float* dec_U = (const float*)d_in[6];
    const float* dec_b = (const float*)d_in[7];
    const float* W_map = (const float*)d_in[8];
    const float* b_map = (const float*)d_in[9];
    const float* W1    = (const float*)d_in[10];
    const float* b1    = (const float*)d_in[11];
    const float* W2    = (const float*)d_in[12];
    const float* b2    = (const float*)d_in[13];
    const float* W3    = (const float*)d_in[14];
    const float* b3    = (const float*)d_in[15];
    const float* W_out = (const float*)d_in[16];
    const float* b_out = (const float*)d_in[17];
    float* out = (float*)d_out;

    set_attrs();

    bf16 *xhi,*xlo,*mhi,*mlo,*hhi,*hlo,*dhi,*dlo,*t1hi,*t1lo,*t2hi,*t2lo;
    bf16 *eWh,*eWl,*dWh,*dWl,*eUh,*eUl,*dUh,*dUl,*wmh,*wml,*w1h,*w1l,*w2h,*w2l,*w3h,*w3l,*woh,*wol;
    float *xw,*z,*c;
    cudaGetSymbolAddress((void**)&xhi, g_xhi);  cudaGetSymbolAddress((void**)&xlo, g_xlo);
    cudaGetSymbolAddress((void**)&mhi, g_mhi);  cudaGetSymbolAddress((void**)&mlo, g_mlo);
    cudaGetSymbolAddress((void**)&hhi, g_hhi);  cudaGetSymbolAddress((void**)&hlo, g_hlo);
    cudaGetSymbolAddress((void**)&dhi, g_dhi);  cudaGetSymbolAddress((void**)&dlo, g_dlo);
    cudaGetSymbolAddress((void**)&t1hi, g_t1hi); cudaGetSymbolAddress((void**)&t1lo, g_t1lo);
    cudaGetSymbolAddress((void**)&t2hi, g_t2hi); cudaGetSymbolAddress((void**)&t2lo, g_t2lo);
    cudaGetSymbolAddress((void**)&eWh, w_encW_hi); cudaGetSymbolAddress((void**)&eWl, w_encW_lo);
    cudaGetSymbolAddress((void**)&dWh, w_decW_hi); cudaGetSymbolAddress((void**)&dWl, w_decW_lo);
    cudaGetSymbolAddress((void**)&eUh, w_encU_hi); cudaGetSymbolAddress((void**)&eUl, w_encU_lo);
    cudaGetSymbolAddress((void**)&dUh, w_decU_hi); cudaGetSymbolAddress((void**)&dUl, w_decU_lo);
    cudaGetSymbolAddress((void**)&wmh, w_map_hi);  cudaGetSymbolAddress((void**)&wml, w_map_lo);
    cudaGetSymbolAddress((void**)&w1h, w_1_hi);    cudaGetSymbolAddress((void**)&w1l, w_1_lo);
    cudaGetSymbolAddress((void**)&w2h, w_2_hi);    cudaGetSymbolAddress((void**)&w2l, w_2_lo);
    cudaGetSymbolAddress((void**)&w3h, w_3_hi);    cudaGetSymbolAddress((void**)&w3l, w_3_lo);
    cudaGetSymbolAddress((void**)&woh, w_out_hi);  cudaGetSymbolAddress((void**)&wol, w_out_lo);
    cudaGetSymbolAddress((void**)&xw, g_xw);
    cudaGetSymbolAddress((void**)&z,  g_z);
    cudaGetSymbolAddress((void**)&c,  g_c);

    // init states + padding tails
    cudaMemsetAsync(c,   0, (size_t)BSZ * UU * sizeof(float));
    cudaMemsetAsync(hhi, 0, (size_t)BSZ * HPAD * sizeof(bf16));
    cudaMemsetAsync(hlo, 0, (size_t)BSZ * HPAD * sizeof(bf16));
    cudaMemsetAsync(dhi, 0, (size_t)BSZ * DPAD * sizeof(bf16));
    cudaMemsetAsync(dlo, 0, (size_t)BSZ * DPAD * sizeof(bf16));

    // weight prep (transpose + hi/lo split, padded)
    auto pw = [](const float* W, int K, int N, int Kpad, int Npad, bf16* hi, bf16* lo) {
        int total = Npad * Kpad;
        prep_weight<<<(total + 255) / 256, 256>>>(W, K, N, Kpad, total, hi, lo);
    };
    pw(enc_W, FENC, GATES, XPAD, GNPAD, eWh, eWl);
    pw(dec_W, FDEC, GATES, MPAD, GNPAD, dWh, dWl);
    pw(enc_U, UU,   GATES, HPAD, GNPAD, eUh, eUl);
    pw(dec_U, UU,   GATES, HPAD, GNPAD, dUh, dUl);
    pw(W_map, TS*UU, H1, DPAD, H1, wmh, wml);
    pw(W1, H1, H1, H1, H1, w1h, w1l);
    pw(W2, H1, H1, H1, H1, w2h, w2l);
    pw(W3, H1, H1, H1, H1, w3h, w3l);
    pw(W_out, H1, OUTN, H1, ONPAD, woh, wol);

    // activation prep
    {
        int tot = BT * XPAD;
        prep_act<<<(tot + 255) / 256, 256>>>(x, tot, FENC, XPAD, xhi, xlo);
        tot = BT * MPAD;
        prep_act<<<(tot + 255) / 256, 256>>>(m, tot, FDEC, MPAD, mhi, mlo);
    }

    const int gate_grid = (BSZ * UU + 255) / 256;

    // encoder input projection: xw = x @ enc_W + enc_b
    launch_mma<0, true, false, true, false>(BT, GATES, XPAD, xhi, xlo, eWh, eWl,
                                            enc_b, nullptr, 0, xw, GATES, nullptr, nullptr, 0);
    for (int t = 0; t < TS; t++) {
        launch_mma<0, false, true, true, false>(BSZ, GATES, HPAD, hhi, hlo, eUh, eUl,
                                                nullptr, xw + (size_t)t * GATES, TS * GATES,
                                                z, GATES, nullptr, nullptr, 0);
        lstm_gates<<<gate_grid, 256>>>(z, c, hhi, hlo, nullptr, nullptr, 0);
    }

    // decoder input projection (reuse xw)
    launch_mma<0, true, false, true, false>(BT, GATES, MPAD, mhi, mlo, dWh, dWl,
                                            dec_b, nullptr, 0, xw, GATES, nullptr, nullptr, 0);
    for (int t = 0; t < TS; t++) {
        launch_mma<0, false, true, true, false>(BSZ, GATES, HPAD, hhi, hlo, dUh, dUl,
                                                nullptr, xw + (size_t)t * GATES, TS * GATES,
                                                z, GATES, nullptr, nullptr, 0);
        lstm_gates<<<gate_grid, 256>>>(z, c, hhi, hlo, dhi, dlo, t);
    }

    // MLP head
    launch_mma<1, true, false, false, true>(BSZ, H1, DPAD, dhi, dlo, wmh, wml,
                                            b_map, nullptr, 0, nullptr, 0, t1hi, t1lo, H1);
    launch_mma<2, true, false, false, true>(BSZ, H1, H1, t1hi, t1lo, w1h, w1l,
                                            b1, nullptr, 0, nullptr, 0, t2hi, t2lo, H1);
    launch_mma<2, true, false, false, true>(BSZ, H1, H1, t2hi, t2lo, w2h, w2l,
                                            b2, nullptr, 0, nullptr, 0, t1hi, t1lo, H1);
    launch_mma<2, true, false, false, true>(BSZ, H1, H1, t1hi, t1lo, w3h, w3l,
                                            b3, nullptr, 0, nullptr, 0, t2hi, t2lo, H1);
    launch_mma<0, true, false, true, false>(BSZ, OUTN, H1, t2hi, t2lo, woh, wol,
                                            b_out, nullptr, 0, out, OUTN, nullptr, nullptr, 0);
}